// round 4
// baseline (speedup 1.0000x reference)
#include <cuda_runtime.h>
#include <math.h>

#define BATCH 256
#define SEQ   512
#define INP   300
#define HID   128
#define G3    384   // 3*HID, gate order [reset; update; new]

typedef unsigned long long u64;

// ---- f32x2 packed-FMA helpers (sm_100+; ptxas never auto-generates FFMA2) ----
#define FMA_X2(d, a, b, c) \
    asm("fma.rn.f32x2 %0, %1, %2, %3;" : "=l"(d) : "l"(a), "l"(b), "l"(c))

__device__ __forceinline__ float2 upk(u64 v) {
    float2 r;
    asm("mov.b64 {%0,%1}, %2;" : "=f"(r.x), "=f"(r.y) : "l"(v));
    return r;
}

// Scratch: input-to-gate preactivations (incl. b_ih): [B, T, 3H] fp32
__device__ float g_xg[(size_t)BATCH * SEQ * G3];

// ---------------------------------------------------------------------------
// Kernel 1: xg[m,g] = sum_k x[m,k] * W_ih[g,k] + b_ih[g]
//   M=131072, N=384, K=300. BM=128, BN=64, BK=8, 256 thr, 8x4 per thread.
//   f32x2: acc pairs along m; B stored duplicated in smem so {b,b} is a 16B LDS.
// ---------------------------------------------------------------------------
#define BM 128
#define BN 64
#define BK 8
#define TM 8
#define TN 4

__global__ __launch_bounds__(256) void proj_kernel(const float* __restrict__ x,
                                                   const float* __restrict__ W,
                                                   const float* __restrict__ bih) {
    __shared__ __align__(16) float As[BK][BM];        // k-major, m contiguous
    __shared__ __align__(16) float Bsd[BK][BN * 2];   // each B value duplicated

    const int tid = threadIdx.x;
    const int tx  = tid & 15;    // n direction (16*TN = 64)
    const int ty  = tid >> 4;    // m direction (16*TM = 128)
    const int bn0 = blockIdx.x * BN;
    const int bm0 = blockIdx.y * BM;

    // acc2[i2][j]: packed pair {acc[2*i2][j], acc[2*i2+1][j]}
    u64 acc2[TM / 2][TN];
    #pragma unroll
    for (int i = 0; i < TM / 2; i++)
        #pragma unroll
        for (int j = 0; j < TN; j++) acc2[i][j] = 0ULL;

    // per-thread tile-load coords (float4 along k)
    const int lm = tid >> 1;     // 0..127 : m row for A
    const int lq = tid & 1;      // 0/1    : which float4 within BK
    const int bn = tid >> 1;     // 0..63  : n row for B (tid<128 only)

    const int KT = (INP + BK - 1) / BK;  // 38, last partially OOB (INP%8==4)
    for (int it = 0; it < KT; it++) {
        const int k0 = it * BK;
        const int kq = k0 + 4 * lq;

        // A tile: 1024 elems = 256 float4, 1 per thread
        float4 av = make_float4(0.f, 0.f, 0.f, 0.f);
        if (kq < INP) av = *(const float4*)&x[(size_t)(bm0 + lm) * INP + kq];
        As[4 * lq + 0][lm] = av.x;
        As[4 * lq + 1][lm] = av.y;
        As[4 * lq + 2][lm] = av.z;
        As[4 * lq + 3][lm] = av.w;

        // B tile: 512 elems = 128 float4, threads 0..127, duplicated store
        if (tid < 128) {
            float4 bv = make_float4(0.f, 0.f, 0.f, 0.f);
            if (kq < INP) bv = *(const float4*)&W[(size_t)(bn0 + bn) * INP + kq];
            Bsd[4 * lq + 0][2 * bn] = bv.x;  Bsd[4 * lq + 0][2 * bn + 1] = bv.x;
            Bsd[4 * lq + 1][2 * bn] = bv.y;  Bsd[4 * lq + 1][2 * bn + 1] = bv.y;
            Bsd[4 * lq + 2][2 * bn] = bv.z;  Bsd[4 * lq + 2][2 * bn + 1] = bv.z;
            Bsd[4 * lq + 3][2 * bn] = bv.w;  Bsd[4 * lq + 3][2 * bn + 1] = bv.w;
        }
        __syncthreads();

        #pragma unroll
        for (int kk = 0; kk < BK; kk++) {
            // a pairs: (m0,m1),(m2,m3),(m4,m5),(m6,m7) — direct 16B LDS
            ulonglong2 a01 = *(const ulonglong2*)&As[kk][ty * TM];
            ulonglong2 a23 = *(const ulonglong2*)&As[kk][ty * TM + 4];
            // b dup pairs: (b0,b0),(b1,b1),(b2,b2),(b3,b3)
            ulonglong2 b01 = *(const ulonglong2*)&Bsd[kk][tx * TN * 2];
            ulonglong2 b23 = *(const ulonglong2*)&Bsd[kk][tx * TN * 2 + 4];
            u64 a[4] = {a01.x, a01.y, a23.x, a23.y};
            u64 b[4] = {b01.x, b01.y, b23.x, b23.y};
            #pragma unroll
            for (int i = 0; i < 4; i++)
                #pragma unroll
                for (int j = 0; j < 4; j++)
                    FMA_X2(acc2[i][j], a[i], b[j], acc2[i][j]);
        }
        __syncthreads();
    }

    // Epilogue: unpack pairs, add bias, float4 stores
    float4 bi = *((const float4*)&bih[bn0 + tx * TN]);
    #pragma unroll
    for (int i2 = 0; i2 < TM / 2; i2++) {
        float2 p0 = upk(acc2[i2][0]);
        float2 p1 = upk(acc2[i2][1]);
        float2 p2 = upk(acc2[i2][2]);
        float2 p3 = upk(acc2[i2][3]);
        size_t m = (size_t)bm0 + ty * TM + 2 * i2;
        float4 o0 = make_float4(p0.x + bi.x, p1.x + bi.y, p2.x + bi.z, p3.x + bi.w);
        float4 o1 = make_float4(p0.y + bi.x, p1.y + bi.y, p2.y + bi.z, p3.y + bi.w);
        *((float4*)&g_xg[m * G3 + bn0 + tx * TN]) = o0;
        *((float4*)&g_xg[(m + 1) * G3 + bn0 + tx * TN]) = o1;
    }
}

// ---------------------------------------------------------------------------
// Kernel 2: GRU recurrence. 2 batch rows per CTA -> grid=128 (ONE wave).
//   Thread g owns W_hh row g as 64 packed f32x2 regs; per step computes both
//   batches' dots with 128 FFMA2 (same FMA-pipe cost as 1 batch of scalar FFMA).
// ---------------------------------------------------------------------------
__global__ __launch_bounds__(384) void gru_kernel(const float* __restrict__ W_hh,
                                                  const float* __restrict__ b_hh,
                                                  const float* __restrict__ W_out,
                                                  const float* __restrict__ b_out,
                                                  float* __restrict__ out) {
    __shared__ __align__(16) float h0s[HID];
    __shared__ __align__(16) float h1s[HID];
    __shared__ float hg0s[G3], hg1s[G3];
    __shared__ float xg0s[G3], xg1s[G3];
    __shared__ float lg[4];

    const int g  = threadIdx.x;
    const int b0 = blockIdx.x * 2;

    // W_hh row g as 64 packed f32x2 (k-pairs) in registers
    u64 wp[HID / 2];
    {
        const ulonglong2* wr = (const ulonglong2*)(W_hh + g * HID);
        #pragma unroll
        for (int q = 0; q < HID / 4; q++) {
            ulonglong2 t = wr[q];
            wp[2 * q]     = t.x;
            wp[2 * q + 1] = t.y;
        }
    }
    const float bh = b_hh[g];

    if (g < HID) { h0s[g] = 0.f; h1s[g] = 0.f; }
    __syncthreads();

    const float* xp0 = g_xg + (size_t)b0 * SEQ * G3 + g;
    const float* xp1 = xp0 + (size_t)SEQ * G3;
    float xv0n = xp0[0];
    float xv1n = xp1[0];

    for (int t = 0; t < SEQ; t++) {
        const float xv0 = xv0n;
        const float xv1 = xv1n;
        if (t + 1 < SEQ) {
            xv0n = xp0[(size_t)(t + 1) * G3];   // prefetch next step
            xv1n = xp1[(size_t)(t + 1) * G3];
        }

        // both dots: 64 broadcast LDS.128 + 128 FFMA2
        u64 a0 = 0ULL, a1 = 0ULL, c0 = 0ULL, c1 = 0ULL;
        const ulonglong2* h04 = (const ulonglong2*)h0s;
        const ulonglong2* h14 = (const ulonglong2*)h1s;
        #pragma unroll
        for (int q = 0; q < HID / 4; q++) {
            ulonglong2 hv0 = h04[q];
            ulonglong2 hv1 = h14[q];
            FMA_X2(a0, wp[2 * q],     hv0.x, a0);
            FMA_X2(a1, wp[2 * q + 1], hv0.y, a1);
            FMA_X2(c0, wp[2 * q],     hv1.x, c0);
            FMA_X2(c1, wp[2 * q + 1], hv1.y, c1);
        }
        {
            float2 s0 = upk(a0), s1 = upk(a1);
            hg0s[g] = (s0.x + s0.y) + (s1.x + s1.y) + bh;
            float2 s2 = upk(c0), s3 = upk(c1);
            hg1s[g] = (s2.x + s2.y) + (s3.x + s3.y) + bh;
        }
        xg0s[g] = xv0;
        xg1s[g] = xv1;
        __syncthreads();   // dots done reading h; hg/xg visible

        if (g < 256) {                       // 256 threads do gate math (2 batches)
            const int  j   = g & (HID - 1);
            float*       hS  = (g < HID) ? h0s  : h1s;
            const float* hgS = (g < HID) ? hg0s : hg1s;
            const float* xgS = (g < HID) ? xg0s : xg1s;
            float r  = 1.f / (1.f + __expf(-(xgS[j] + hgS[j])));
            float z  = 1.f / (1.f + __expf(-(xgS[j + HID] + hgS[j + HID])));
            float n  = tanhf(xgS[j + 2 * HID] + r * hgS[j + 2 * HID]);
            hS[j] = (1.f - z) * n + z * hS[j];
        }
        __syncthreads();   // new h visible for next step
    }

    // ---- fused classifier: relu -> linear(2) -> log_softmax, both batches ----
    if (g < 4) {
        const int cls = g & 1;
        const int bb  = g >> 1;
        const float* hS = bb ? h1s : h0s;
        const float* wo = W_out + cls * HID;
        float s = 0.f;
        #pragma unroll
        for (int j = 0; j < HID; j++) s = fmaf(wo[j], fmaxf(hS[j], 0.f), s);
        lg[g] = s + b_out[cls];
    }
    __syncthreads();
    if (g < 2) {           // g = local batch index
        float l0 = lg[2 * g], l1 = lg[2 * g + 1];
        float mx = fmaxf(l0, l1);
        float lse = mx + logf(expf(l0 - mx) + expf(l1 - mx));
        out[(b0 + g) * 2 + 0] = l0 - lse;
        out[(b0 + g) * 2 + 1] = l1 - lse;
    }
}

// ---------------------------------------------------------------------------
extern "C" void kernel_launch(void* const* d_in, const int* in_sizes, int n_in,
                              void* d_out, int out_size) {
    const float* x     = (const float*)d_in[0];
    const float* W_ih  = (const float*)d_in[1];
    const float* W_hh  = (const float*)d_in[2];
    const float* b_ih  = (const float*)d_in[3];
    const float* b_hh  = (const float*)d_in[4];
    const float* W_out = (const float*)d_in[5];
    const float* b_out = (const float*)d_in[6];
    float* out = (float*)d_out;

    dim3 pgrid(G3 / BN, (BATCH * SEQ) / BM);   // 6 x 1024
    proj_kernel<<<pgrid, 256>>>(x, W_ih, b_ih);
    gru_kernel<<<BATCH / 2, 384>>>(W_hh, b_hh, W_out, b_out, out);
}

// round 5
// speedup vs baseline: 1.4101x; 1.4101x over previous
#include <cuda_runtime.h>
#include <math.h>

#define BATCH 256
#define SEQ   512
#define INP   300
#define HID   128
#define G3    384   // 3*HID, gate order [reset; update; new]

typedef unsigned long long u64;

// ---- f32x2 packed FMA (sm_100+; ptxas never auto-emits FFMA2) ----
#define FMA_X2(d, a, b, c) \
    asm("fma.rn.f32x2 %0, %1, %2, %3;" : "=l"(d) : "l"(a), "l"(b), "l"(c))

__device__ __forceinline__ float2 upk(u64 v) {
    float2 r;
    asm("mov.b64 {%0,%1}, %2;" : "=f"(r.x), "=f"(r.y) : "l"(v));
    return r;
}

// fast, accurate-enough activations (MUFU-based; no div.rn, no poly tanh)
__device__ __forceinline__ float sigf(float x) {
    return __fdividef(1.f, 1.f + __expf(-x));      // err ~ulp; x->-inf => 0
}
__device__ __forceinline__ float tanhfast(float x) {
    x = fminf(fmaxf(x, -20.f), 20.f);              // keep e^(2x) finite
    float e = __expf(2.f * x);
    return __fdividef(e - 1.f, e + 1.f);
}

// Scratch: input-to-gate preactivations (incl. b_ih): [B, T, 3H] fp32
__device__ float g_xg[(size_t)BATCH * SEQ * G3];

// ---------------------------------------------------------------------------
// Kernel 1: xg[m,g] = sum_k x[m,k] * W_ih[g,k] + b_ih[g]
//   M=131072, N=384, K=300. Scalar-FFMA SGEMM (84%-of-roofline structure from
//   R2), BK raised 8->16 (half the syncs), float4 global tile loads.
// ---------------------------------------------------------------------------
#define BM 128
#define BN 64
#define BK 16
#define TM 8
#define TN 4

__global__ __launch_bounds__(256) void proj_kernel(const float* __restrict__ x,
                                                   const float* __restrict__ W,
                                                   const float* __restrict__ bih) {
    __shared__ __align__(16) float As[BK][BM];   // k-major, m contiguous
    __shared__ __align__(16) float Bs[BK][BN];   // k-major

    const int tid = threadIdx.x;
    const int tx  = tid & 15;    // n direction (16*TN = 64)
    const int ty  = tid >> 4;    // m direction (16*TM = 128)
    const int bn0 = blockIdx.x * BN;
    const int bm0 = blockIdx.y * BM;

    float acc[TM][TN];
    #pragma unroll
    for (int i = 0; i < TM; i++)
        #pragma unroll
        for (int j = 0; j < TN; j++) acc[i][j] = 0.f;

    const int KT = (INP + BK - 1) / BK;   // 19; last tile zero-padded (INP%16==12)
    for (int it = 0; it < KT; it++) {
        const int k0 = it * BK;

        // A tile: 128x16 = 512 float4, 2 per thread
        #pragma unroll
        for (int l = 0; l < 2; l++) {
            int e  = tid + l * 256;
            int m  = e >> 2;
            int q  = e & 3;
            int kq = k0 + 4 * q;
            float4 av = make_float4(0.f, 0.f, 0.f, 0.f);
            if (kq < INP) av = *(const float4*)&x[(size_t)(bm0 + m) * INP + kq];
            As[4 * q + 0][m] = av.x;
            As[4 * q + 1][m] = av.y;
            As[4 * q + 2][m] = av.z;
            As[4 * q + 3][m] = av.w;
        }
        // B tile: 64x16 = 256 float4, 1 per thread
        {
            int n  = tid >> 2;
            int q  = tid & 3;
            int kq = k0 + 4 * q;
            float4 bv = make_float4(0.f, 0.f, 0.f, 0.f);
            if (kq < INP) bv = *(const float4*)&W[(size_t)(bn0 + n) * INP + kq];
            Bs[4 * q + 0][n] = bv.x;
            Bs[4 * q + 1][n] = bv.y;
            Bs[4 * q + 2][n] = bv.z;
            Bs[4 * q + 3][n] = bv.w;
        }
        __syncthreads();

        #pragma unroll
        for (int kk = 0; kk < BK; kk++) {
            float4 av0 = *((const float4*)&As[kk][ty * TM]);
            float4 av1 = *((const float4*)&As[kk][ty * TM + 4]);
            float4 bv  = *((const float4*)&Bs[kk][tx * TN]);
            float a[TM]  = {av0.x, av0.y, av0.z, av0.w, av1.x, av1.y, av1.z, av1.w};
            float bb[TN] = {bv.x, bv.y, bv.z, bv.w};
            #pragma unroll
            for (int i = 0; i < TM; i++)
                #pragma unroll
                for (int j = 0; j < TN; j++)
                    acc[i][j] = fmaf(a[i], bb[j], acc[i][j]);
        }
        __syncthreads();
    }

    float4 bi = *((const float4*)&bih[bn0 + tx * TN]);
    #pragma unroll
    for (int i = 0; i < TM; i++) {
        size_t m = (size_t)bm0 + ty * TM + i;
        float4 o;
        o.x = acc[i][0] + bi.x;
        o.y = acc[i][1] + bi.y;
        o.z = acc[i][2] + bi.z;
        o.w = acc[i][3] + bi.w;
        *((float4*)&g_xg[m * G3 + bn0 + tx * TN]) = o;
    }
}

// ---------------------------------------------------------------------------
// Kernel 2: GRU recurrence. 2 batch rows/CTA, grid=128 (one wave).
//   Thread g holds W_hh row g as 64 f32x2 regs; per step: both batches' dots
//   via FFMA2. Gate threads (g<256) prefetch their 3 xg values from global one
//   step ahead (no xgs smem round-trip). Fast MUFU activations.
// ---------------------------------------------------------------------------
__global__ __launch_bounds__(384) void gru_kernel(const float* __restrict__ W_hh,
                                                  const float* __restrict__ b_hh,
                                                  const float* __restrict__ W_out,
                                                  const float* __restrict__ b_out,
                                                  float* __restrict__ out) {
    __shared__ __align__(16) float h0s[HID];
    __shared__ __align__(16) float h1s[HID];
    __shared__ float hg0s[G3], hg1s[G3];
    __shared__ float lg[4];

    const int g  = threadIdx.x;
    const int b0 = blockIdx.x * 2;

    // W_hh row g as 64 packed f32x2 (k-pairs)
    u64 wp[HID / 2];
    {
        const ulonglong2* wr = (const ulonglong2*)(W_hh + g * HID);
        #pragma unroll
        for (int q = 0; q < HID / 4; q++) {
            ulonglong2 t = wr[q];
            wp[2 * q]     = t.x;
            wp[2 * q + 1] = t.y;
        }
    }
    const float bh = b_hh[g];

    if (g < HID) { h0s[g] = 0.f; h1s[g] = 0.f; }
    __syncthreads();

    // gate threads: g<256; j = g&127, batch = g>>7. Prefetch triple for t=0.
    const float* xq = g_xg + (size_t)(b0 + (g >> 7)) * SEQ * G3 + (g & (HID - 1));
    float x0 = 0.f, x1 = 0.f, x2 = 0.f;
    if (g < 256) {
        x0 = xq[0];
        x1 = xq[HID];
        x2 = xq[2 * HID];
    }

    for (int t = 0; t < SEQ; t++) {
        // prefetch next step's triple (hidden under the dot phase)
        float nx0 = 0.f, nx1 = 0.f, nx2 = 0.f;
        if (g < 256 && t + 1 < SEQ) {
            const float* p = xq + (size_t)(t + 1) * G3;
            nx0 = p[0];
            nx1 = p[HID];
            nx2 = p[2 * HID];
        }

        // both batch dots: 64 broadcast LDS.128 + 128 FFMA2
        u64 a0 = 0ULL, a1 = 0ULL, c0 = 0ULL, c1 = 0ULL;
        const ulonglong2* h04 = (const ulonglong2*)h0s;
        const ulonglong2* h14 = (const ulonglong2*)h1s;
        #pragma unroll
        for (int q = 0; q < HID / 4; q++) {
            ulonglong2 hv0 = h04[q];
            ulonglong2 hv1 = h14[q];
            FMA_X2(a0, wp[2 * q],     hv0.x, a0);
            FMA_X2(a1, wp[2 * q + 1], hv0.y, a1);
            FMA_X2(c0, wp[2 * q],     hv1.x, c0);
            FMA_X2(c1, wp[2 * q + 1], hv1.y, c1);
        }
        {
            float2 s0 = upk(a0), s1 = upk(a1);
            hg0s[g] = (s0.x + s0.y) + (s1.x + s1.y) + bh;
            float2 s2 = upk(c0), s3 = upk(c1);
            hg1s[g] = (s2.x + s2.y) + (s3.x + s3.y) + bh;
        }
        __syncthreads();   // dots done reading h; hg visible

        if (g < 256) {
            const int j = g & (HID - 1);
            float*       hS  = (g < HID) ? h0s  : h1s;
            const float* hgS = (g < HID) ? hg0s : hg1s;
            float r  = sigf(x0 + hgS[j]);
            float z  = sigf(x1 + hgS[j + HID]);
            float n  = tanhfast(x2 + r * hgS[j + 2 * HID]);
            hS[j] = (1.f - z) * n + z * hS[j];
        }
        __syncthreads();   // new h visible for next step

        x0 = nx0; x1 = nx1; x2 = nx2;
    }

    // ---- fused classifier: relu -> linear(2) -> log_softmax, both batches ----
    if (g < 4) {
        const int cls = g & 1;
        const int bb  = g >> 1;
        const float* hS = bb ? h1s : h0s;
        const float* wo = W_out + cls * HID;
        float s = 0.f;
        #pragma unroll
        for (int j = 0; j < HID; j++) s = fmaf(wo[j], fmaxf(hS[j], 0.f), s);
        lg[g] = s + b_out[cls];
    }
    __syncthreads();
    if (g < 2) {           // g = local batch index
        float l0 = lg[2 * g], l1 = lg[2 * g + 1];
        float mx = fmaxf(l0, l1);
        float lse = mx + logf(expf(l0 - mx) + expf(l1 - mx));
        out[(b0 + g) * 2 + 0] = l0 - lse;
        out[(b0 + g) * 2 + 1] = l1 - lse;
    }
}

// ---------------------------------------------------------------------------
extern "C" void kernel_launch(void* const* d_in, const int* in_sizes, int n_in,
                              void* d_out, int out_size) {
    const float* x     = (const float*)d_in[0];
    const float* W_ih  = (const float*)d_in[1];
    const float* W_hh  = (const float*)d_in[2];
    const float* b_ih  = (const float*)d_in[3];
    const float* b_hh  = (const float*)d_in[4];
    const float* W_out = (const float*)d_in[5];
    const float* b_out = (const float*)d_in[6];
    float* out = (float*)d_out;

    dim3 pgrid(G3 / BN, (BATCH * SEQ) / BM);   // 6 x 1024
    proj_kernel<<<pgrid, 256>>>(x, W_ih, b_ih);
    gru_kernel<<<BATCH / 2, 384>>>(W_hh, b_hh, W_out, b_out, out);
}

// round 7
// speedup vs baseline: 2.0343x; 1.4427x over previous
#include <cuda_runtime.h>
#include <cuda_bf16.h>
#include <math.h>

#define BATCH 256
#define SEQ   512
#define INP   300
#define HID   128
#define G3    384
#define KPAD  304          // 19 k-steps of 16
#define KSTEPS 19
#define NTILES 48          // 384 / 8

typedef unsigned long long u64;
typedef unsigned int u32;

// ======================= globals =======================
// xg preactivations WITHOUT b_ih (gru adds it): [B, T, 3H] fp32
__device__ float g_xg[(size_t)BATCH * SEQ * G3];
// W_ih pre-packed in m16n8k16 B-fragment order:
//   [ntile][kstep][lane] -> uint4 {b0_hi, b1_hi, b0_lo, b1_lo}
__device__ uint4 g_Wfrag[NTILES * KSTEPS * 32];

// ---- f32x2 packed FMA for gru ----
#define FMA_X2(d, a, b, c) \
    asm("fma.rn.f32x2 %0, %1, %2, %3;" : "=l"(d) : "l"(a), "l"(b), "l"(c))
__device__ __forceinline__ float2 upk(u64 v) {
    float2 r;
    asm("mov.b64 {%0,%1}, %2;" : "=f"(r.x), "=f"(r.y) : "l"(v));
    return r;
}
__device__ __forceinline__ float sigf(float x) {
    return __fdividef(1.f, 1.f + __expf(-x));
}
__device__ __forceinline__ float tanhfast(float x) {
    x = fminf(fmaxf(x, -20.f), 20.f);
    float e = __expf(2.f * x);
    return __fdividef(e - 1.f, e + 1.f);
}

// bf16 pair pack: lo half = first (lower-k) element
__device__ __forceinline__ u32 pack_bf2(float v0, float v1) {
    union { __nv_bfloat162 b; u32 u; } t;
    t.b = __halves2bfloat162(__float2bfloat16(v0), __float2bfloat16(v1));
    return t.u;
}
__device__ __forceinline__ u32 pack_bf2_lo(float v0, float v1) {
    __nv_bfloat16 h0 = __float2bfloat16(v0);
    __nv_bfloat16 h1 = __float2bfloat16(v1);
    union { __nv_bfloat162 b; u32 u; } t;
    t.b = __halves2bfloat162(__float2bfloat16(v0 - __bfloat162float(h0)),
                             __float2bfloat16(v1 - __bfloat162float(h1)));
    return t.u;
}

#define MMA_BF16(c, a0, a1, a2, a3, b0, b1)                                   \
    asm volatile("mma.sync.aligned.m16n8k16.row.col.f32.bf16.bf16.f32 "       \
                 "{%0,%1,%2,%3}, {%4,%5,%6,%7}, {%8,%9}, {%0,%1,%2,%3};"      \
                 : "+f"((c)[0]), "+f"((c)[1]), "+f"((c)[2]), "+f"((c)[3])     \
                 : "r"(a0), "r"(a1), "r"(a2), "r"(a3), "r"(b0), "r"(b1))

// ---------------------------------------------------------------------------
// Prep: W_ih [384 x 300] fp32 -> fragment-ordered bf16 hi/lo image.
//   b0 = {W[n][2t], W[n][2t+1]},  b1 = {W[n][2t+8], W[n][2t+9]},  t = lane%4,
//   n = ntile*8 + lane/4, k base = kstep*16.
// ---------------------------------------------------------------------------
__global__ void prep_kernel(const float* __restrict__ W) {
    int idx = blockIdx.x * blockDim.x + threadIdx.x;    // 48*19*32 = 29184
    if (idx >= NTILES * KSTEPS * 32) return;
    int nt   = idx / (KSTEPS * 32);
    int rem  = idx % (KSTEPS * 32);
    int ks   = rem >> 5;
    int lane = rem & 31;
    int n    = nt * 8 + (lane >> 2);
    int k0   = ks * 16 + 2 * (lane & 3);

    const float* wr = W + (size_t)n * INP;
    float v0 = (k0     < INP) ? wr[k0]     : 0.f;
    float v1 = (k0 + 1 < INP) ? wr[k0 + 1] : 0.f;
    float v2 = (k0 + 8 < INP) ? wr[k0 + 8] : 0.f;
    float v3 = (k0 + 9 < INP) ? wr[k0 + 9] : 0.f;

    uint4 o;
    o.x = pack_bf2(v0, v1);
    o.y = pack_bf2(v2, v3);
    o.z = pack_bf2_lo(v0, v1);
    o.w = pack_bf2_lo(v2, v3);
    g_Wfrag[idx] = o;
}

// ---------------------------------------------------------------------------
// Proj: xg[m,g] = sum_k x[m,k] * W[g,k] via mma.sync bf16x3 (no bias).
//   grid = 1024 CTAs x 256 thr (8 warps). Warp w owns m-tile rows
//   [bm0 + 16w, +16). N done in 4 chunks of 12 n-tiles; C in registers.
//   No smem, no block syncs.
// ---------------------------------------------------------------------------
__global__ __launch_bounds__(256) void proj_mma_kernel(const float* __restrict__ x) {
    const int tid  = threadIdx.x;
    const int wid  = tid >> 5;
    const int lane = tid & 31;
    const int gid  = lane >> 2;     // group id (row within tile / n within tile)
    const int tig  = lane & 3;      // thread in group (k-pair selector)
    const int bm0  = blockIdx.x * 128;

    const int r0 = bm0 + wid * 16 + gid;   // A row for a0/a2, c0/c1
    const int r1 = r0 + 8;                 // A row for a1/a3, c2/c3
    const float* xr0 = x + (size_t)r0 * INP;
    const float* xr1 = x + (size_t)r1 * INP;

    for (int nc = 0; nc < 4; nc++) {
        float C[12][4];
        #pragma unroll
        for (int i = 0; i < 12; i++)
            #pragma unroll
            for (int j = 0; j < 4; j++) C[i][j] = 0.f;

        for (int ks = 0; ks < KSTEPS; ks++) {
            const int k0 = ks * 16 + 2 * tig;      // always < 300 (max 294)
            // ---- A fragments (fp32 -> bf16 hi/lo in registers) ----
            float2 p00 = *(const float2*)(xr0 + k0);
            float2 p10 = *(const float2*)(xr1 + k0);
            float2 p01 = make_float2(0.f, 0.f);
            float2 p11 = make_float2(0.f, 0.f);
            if (k0 + 8 < INP) {                    // pair never straddles 300
                p01 = *(const float2*)(xr0 + k0 + 8);
                p11 = *(const float2*)(xr1 + k0 + 8);
            }
            u32 ah0 = pack_bf2(p00.x, p00.y), al0 = pack_bf2_lo(p00.x, p00.y);
            u32 ah1 = pack_bf2(p10.x, p10.y), al1 = pack_bf2_lo(p10.x, p10.y);
            u32 ah2 = pack_bf2(p01.x, p01.y), al2 = pack_bf2_lo(p01.x, p01.y);
            u32 ah3 = pack_bf2(p11.x, p11.y), al3 = pack_bf2_lo(p11.x, p11.y);

            const uint4* bp = g_Wfrag + ((size_t)(nc * 12) * KSTEPS + ks) * 32 + lane;
            #pragma unroll
            for (int ntl = 0; ntl < 12; ntl++) {
                uint4 B = bp[(size_t)ntl * KSTEPS * 32];
                MMA_BF16(C[ntl], ah0, ah1, ah2, ah3, B.x, B.y);  // hi*hi
                MMA_BF16(C[ntl], ah0, ah1, ah2, ah3, B.z, B.w);  // hi*lo
                MMA_BF16(C[ntl], al0, al1, al2, al3, B.x, B.y);  // lo*hi
            }
        }

        // ---- store C: c0/c1 -> row r0, c2/c3 -> row r1, cols n0,n0+1 ----
        #pragma unroll
        for (int ntl = 0; ntl < 12; ntl++) {
            const int n0 = (nc * 12 + ntl) * 8 + 2 * tig;
            *(float2*)(g_xg + (size_t)r0 * G3 + n0) = make_float2(C[ntl][0], C[ntl][1]);
            *(float2*)(g_xg + (size_t)r1 * G3 + n0) = make_float2(C[ntl][2], C[ntl][3]);
        }
    }
}

// ---------------------------------------------------------------------------
// GRU recurrence (R5 structure). 2 batch rows/CTA, grid=128 (one wave);
// W_hh row in 64 f32x2 regs; FFMA2 dots; MUFU gates; b_ih added here.
// ---------------------------------------------------------------------------
__global__ __launch_bounds__(384) void gru_kernel(const float* __restrict__ W_hh,
                                                  const float* __restrict__ b_ih,
                                                  const float* __restrict__ b_hh,
                                                  const float* __restrict__ W_out,
                                                  const float* __restrict__ b_out,
                                                  float* __restrict__ out) {
    __shared__ __align__(16) float h0s[HID];
    __shared__ __align__(16) float h1s[HID];
    __shared__ float hg0s[G3], hg1s[G3];
    __shared__ float lg[4];

    const int g  = threadIdx.x;
    const int b0 = blockIdx.x * 2;

    u64 wp[HID / 2];
    {
        const ulonglong2* wr = (const ulonglong2*)(W_hh + g * HID);
        #pragma unroll
        for (int q = 0; q < HID / 4; q++) {
            ulonglong2 t = wr[q];
            wp[2 * q]     = t.x;
            wp[2 * q + 1] = t.y;
        }
    }
    const float bh = b_hh[g];

    if (g < HID) { h0s[g] = 0.f; h1s[g] = 0.f; }
    __syncthreads();

    const int j = g & (HID - 1);
    const float* xq = g_xg + (size_t)(b0 + (g >> 7)) * SEQ * G3 + j;
    float x0 = 0.f, x1 = 0.f, x2 = 0.f, bi0 = 0.f, bi1 = 0.f, bi2 = 0.f;
    if (g < 256) {
        bi0 = b_ih[j]; bi1 = b_ih[j + HID]; bi2 = b_ih[j + 2 * HID];
        x0 = xq[0]; x1 = xq[HID]; x2 = xq[2 * HID];
    }

    for (int t = 0; t < SEQ; t++) {
        float nx0 = 0.f, nx1 = 0.f, nx2 = 0.f;
        if (g < 256 && t + 1 < SEQ) {
            const float* p = xq + (size_t)(t + 1) * G3;
            nx0 = p[0]; nx1 = p[HID]; nx2 = p[2 * HID];
        }

        u64 a0 = 0ULL, a1 = 0ULL, c0 = 0ULL, c1 = 0ULL;
        const ulonglong2* h04 = (const ulonglong2*)h0s;
        const ulonglong2* h14 = (const ulonglong2*)h1s;
        #pragma unroll
        for (int q = 0; q < HID / 4; q++) {
            ulonglong2 hv0 = h04[q];
            ulonglong2 hv1 = h14[q];
            FMA_X2(a0, wp[2 * q],     hv0.x, a0);
            FMA_X2(a1, wp[2 * q + 1], hv0.y, a1);
            FMA_X2(c0, wp[2 * q],     hv1.x, c0);
            FMA_X2(c1, wp[2 * q + 1], hv1.y, c1);
        }
        {
            float2 s0 = upk(a0), s1 = upk(a1);
            hg0s[g] = (s0.x + s0.y) + (s1.x + s1.y) + bh;
            float2 s2 = upk(c0), s3 = upk(c1);
            hg1s[g] = (s2.x + s2.y) + (s3.x + s3.y) + bh;
        }
        __syncthreads();

        if (g < 256) {
            float*       hS  = (g < HID) ? h0s  : h1s;
            const float* hgS = (g < HID) ? hg0s : hg1s;
            float r  = sigf(x0 + bi0 + hgS[j]);
            float z  = sigf(x1 + bi1 + hgS[j + HID]);
            float n  = tanhfast(x2 + bi2 + r * hgS[j + 2 * HID]);
            hS[j] = (1.f - z) * n + z * hS[j];
        }
        __syncthreads();

        x0 = nx0; x1 = nx1; x2 = nx2;
    }

    if (g < 4) {
        const int cls = g & 1;
        const float* hS = (g >> 1) ? h1s : h0s;
        const float* wo = W_out + cls * HID;
        float s = 0.f;
        #pragma unroll
        for (int k = 0; k < HID; k++) s = fmaf(wo[k], fmaxf(hS[k], 0.f), s);
        lg[g] = s + b_out[cls];
    }
    __syncthreads();
    if (g < 2) {
        float l0 = lg[2 * g], l1 = lg[2 * g + 1];
        float mx = fmaxf(l0, l1);
        float lse = mx + logf(expf(l0 - mx) + expf(l1 - mx));
        out[(b0 + g) * 2 + 0] = l0 - lse;
        out[(b0 + g) * 2 + 1] = l1 - lse;
    }
}

// ---------------------------------------------------------------------------
extern "C" void kernel_launch(void* const* d_in, const int* in_sizes, int n_in,
                              void* d_out, int out_size) {
    const float* x     = (const float*)d_in[0];
    const float* W_ih  = (const float*)d_in[1];
    const float* W_hh  = (const float*)d_in[2];
    const float* b_ih  = (const float*)d_in[3];
    const float* b_hh  = (const float*)d_in[4];
    const float* W_out = (const float*)d_in[5];
    const float* b_out = (const float*)d_in[6];
    float* out = (float*)d_out;

    prep_kernel<<<(NTILES * KSTEPS * 32) / 256, 256>>>(W_ih);         // 114 blocks
    proj_mma_kernel<<<(BATCH * SEQ) / 128, 256>>>(x);                 // 1024 blocks
    gru_kernel<<<BATCH / 2, 384>>>(W_hh, b_ih, b_hh, W_out, b_out, out);
}